// round 12
// baseline (speedup 1.0000x reference)
#include <cuda_runtime.h>
#include <cuda_fp16.h>
#include <cstdint>

// QuantizedCodebook: inputs [32,4096,64] f32, codebook [1024,64] f32.
// Output (f32 concat): [ loss(1) | z_q(N*64) | indices-as-f32(N) ]
//
// R11: SINGLE fp16-plane HMMA (approx = xh*ch). Rigorous per-row error bound
// B = ||xl||*maxC + ||xh||*maxCl (exact norms) => margin ~9e-3. Per-thread
// top-2 -> quad-merged true row top-2. Certified if s2-s1 > margin, else
// CTA-cooperative exact scan of all 1024 codes (~0.5us/row, ~5% of rows).
// Exact fp32 z_q / loss. 3x less tensor work than R8, half the instr stream.

#define D 64
#define KCODES 1024
#define TPB 256
#define ROWS_PER_CTA 128
#define CHUNK_N 64
#define NCHUNKS (KCODES / CHUNK_N)   // 16
#define NK 4                          // K=64 -> 4 k16 steps
#define RSA 144                       // A row: 64 fp16 + 16B pad
#define RSB 144                       // B row: 64 fp16 + 16B pad

// dynamic smem layout
#define SM_B0   0                     // 64*144 = 9216  (A-stage overlaps B0+B1)
#define SM_B1   9216
#define SM_CS   18432                 // csqr[1024] (4096)
#define SM_M    22528                 // float2 top2 scores [128]
#define SM_I    23552                 // int2   top2 idx    [128]
#define SM_BIDX 24576                 // int bidx[128]
#define SM_LIST 25088                 // int list[128]
#define SM_CNT  25600                 // int
#define SM_REDS 25608                 // float[8]
#define SM_REDI 25640                 // int[8]
#define SMEM_TOTAL 25728

__device__ double g_loss_accum;
__device__ unsigned int g_ticket;
__device__ float g_maxc2 = 0.0f;     // max ||c||^2
__device__ float g_maxcl2 = 0.0f;    // max ||c - fp16(c)||^2
__device__ float g_csqr[KCODES];
__device__ unsigned int g_cb16[KCODES * 32];   // per code: 64 fp16

// ---------------- helpers ----------------
__device__ __forceinline__ uint32_t smem_u32(const void* p) {
    uint32_t a;
    asm("{ .reg .u64 t; cvta.to.shared.u64 t, %1; cvt.u32.u64 %0, t; }"
        : "=r"(a) : "l"(p));
    return a;
}
__device__ __forceinline__ uint32_t packh(float a, float b) {   // lo=a, hi=b
    uint32_t r;
    asm("cvt.rn.f16x2.f32 %0, %1, %2;" : "=r"(r) : "f"(b), "f"(a));
    return r;
}
__device__ __forceinline__ float2 unph(uint32_t h) {
    __half2 hh = *reinterpret_cast<__half2*>(&h);
    return __half22float2(hh);
}
__device__ __forceinline__ void ldsm4(uint32_t& r0, uint32_t& r1,
                                      uint32_t& r2, uint32_t& r3, uint32_t a) {
    asm volatile("ldmatrix.sync.aligned.m8n8.x4.shared.b16 {%0,%1,%2,%3}, [%4];"
                 : "=r"(r0), "=r"(r1), "=r"(r2), "=r"(r3) : "r"(a));
}
__device__ __forceinline__ void mma16816(float& c0, float& c1, float& c2, float& c3,
                                         uint32_t a0, uint32_t a1, uint32_t a2,
                                         uint32_t a3, uint32_t b0, uint32_t b1) {
    asm("mma.sync.aligned.m16n8k16.row.col.f32.f16.f16.f32 "
        "{%0,%1,%2,%3}, {%4,%5,%6,%7}, {%8,%9}, {%0,%1,%2,%3};"
        : "+f"(c0), "+f"(c1), "+f"(c2), "+f"(c3)
        : "r"(a0), "r"(a1), "r"(a2), "r"(a3), "r"(b0), "r"(b1));
}
__device__ __forceinline__ void cpa16(uint32_t dst, const void* src) {
    asm volatile("cp.async.cg.shared.global [%0], [%1], 16;"
                 :: "r"(dst), "l"(src));
}
#define CP_COMMIT() asm volatile("cp.async.commit_group;" ::: "memory")
#define CP_WAIT0()  asm volatile("cp.async.wait_group 0;" ::: "memory")

__device__ __forceinline__ void ins2(float v, int idx,
                                     float& s1, int& i1, float& s2, int& i2) {
    if (v < s2) {
        if (v < s1) { s2 = s1; i2 = i1; s1 = v; i1 = idx; }
        else        { s2 = v;  i2 = idx; }
    }
}

// ---------------- kernel 1: prep ----------------
__global__ void vq_prep_kernel(const float* __restrict__ codebook) {
    int j = blockIdx.x * blockDim.x + threadIdx.x;
    if (j == 0) { g_loss_accum = 0.0; g_ticket = 0u; }
    if (j >= KCODES) return;
    const float4* c4 = (const float4*)(codebook + (size_t)j * D);
    unsigned int* q = g_cb16 + (size_t)j * 32;
    float s = 0.0f, cl2 = 0.0f;
    #pragma unroll
    for (int i = 0; i < 16; i++) {
        float4 v = c4[i];
        s += v.x * v.x + v.y * v.y + v.z * v.z + v.w * v.w;
        uint32_t h0 = packh(v.x, v.y), h1 = packh(v.z, v.w);
        float2 f0 = unph(h0), f1 = unph(h1);
        float r0 = v.x - f0.x, r1 = v.y - f0.y;
        float r2 = v.z - f1.x, r3 = v.w - f1.y;
        cl2 += r0 * r0 + r1 * r1 + r2 * r2 + r3 * r3;
        q[2 * i] = h0; q[2 * i + 1] = h1;
    }
    g_csqr[j] = s;
    atomicMax((int*)&g_maxc2, __float_as_int(s));
    atomicMax((int*)&g_maxcl2, __float_as_int(cl2));
}

// ---------------- kernel 2: main ----------------
__global__ void __launch_bounds__(TPB, 3)
vq_main_kernel(const float* __restrict__ inp,
               const float* __restrict__ codebook,
               float* __restrict__ out, int n_rows) {
    extern __shared__ char dsm[];
    const uint32_t sbase = smem_u32(dsm);
    float*  s_csqr = (float*)(dsm + SM_CS);
    float2* s_m    = (float2*)(dsm + SM_M);
    int2*   s_i    = (int2*)(dsm + SM_I);
    int*    s_bidx = (int*)(dsm + SM_BIDX);
    int*    s_list = (int*)(dsm + SM_LIST);
    int*    s_cnt  = (int*)(dsm + SM_CNT);
    float*  s_reds = (float*)(dsm + SM_REDS);
    int*    s_redi = (int*)(dsm + SM_REDI);

    const int tid = threadIdx.x;
    const int l = tid & 31;
    const int w = tid >> 5;
    const int row0 = blockIdx.x * ROWS_PER_CTA;

    if (tid == 0) *s_cnt = 0;

    // ---- stage A [128 rows][64 fp16] stride 144 (overlaps B0+B1 exactly) ----
    if (tid < ROWS_PER_CTA) {
        const float4* xr = (const float4*)(inp + (size_t)(row0 + tid) * D);
        uint32_t* arow = (uint32_t*)(dsm + tid * RSA);
        #pragma unroll
        for (int i = 0; i < 16; i++) {
            float4 v = xr[i];
            arow[2 * i]     = packh(v.x, v.y);
            arow[2 * i + 1] = packh(v.z, v.w);
        }
    }
    for (int g = tid; g < KCODES; g += TPB) s_csqr[g] = g_csqr[g];
    __syncthreads();

    // ---- preload A fragments (held all kernel): 4 k-steps ----
    uint32_t af[NK][4];
    {
        uint32_t aoff = (uint32_t)((w * 16 + (l & 15)) * RSA + ((l & 16) ? 16 : 0));
        #pragma unroll
        for (int k = 0; k < NK; k++)
            ldsm4(af[k][0], af[k][1], af[k][2], af[k][3], sbase + aoff + k * 32);
    }
    __syncthreads();   // A reads done before B overwrites region

    float sA1 = 3.4e38f, sA2 = 3.4e38f, sB1 = 3.4e38f, sB2 = 3.4e38f;
    int iA1 = 0, iA2 = 0, iB1 = 0, iB2 = 0;

    const uint32_t boff = (uint32_t)(((l & 7) + ((l & 16) ? 8 : 0)) * RSB
                                     + ((l & 8) ? 16 : 0));
    const int q2 = 2 * (l & 3);
    const uint4* cb4 = (const uint4*)g_cb16;
    const uint32_t bb[2] = { sbase + SM_B0, sbase + SM_B1 };

    // prefetch chunk 0: 64 codes x 128B = 512 x 16B (2 per thread)
    #pragma unroll
    for (int g = tid; g < CHUNK_N * 8; g += TPB) {
        int r = g >> 3, c = g & 7;
        cpa16(bb[0] + (uint32_t)(r * RSB + c * 16), cb4 + (size_t)r * 8 + c);
    }
    CP_COMMIT();

    for (int t = 0; t < NCHUNKS; t++) {
        CP_WAIT0();
        __syncthreads();
        if (t + 1 < NCHUNKS) {
            const uint4* src = cb4 + (size_t)(t + 1) * CHUNK_N * 8;
            uint32_t dstb = bb[(t + 1) & 1];
            #pragma unroll
            for (int g = tid; g < CHUNK_N * 8; g += TPB) {
                int r = g >> 3, c = g & 7;
                cpa16(dstb + (uint32_t)(r * RSB + c * 16), src + (size_t)r * 8 + c);
            }
            CP_COMMIT();
        }
        const uint32_t bch = bb[t & 1];

        // ---- 64 codes: 8 accumulator sets (chains), depth-4 ----
        float acc[8][4];
        #pragma unroll
        for (int s = 0; s < 8; s++)
            acc[s][0] = acc[s][1] = acc[s][2] = acc[s][3] = 0.f;
        #pragma unroll
        for (int k = 0; k < NK; k++) {
            uint32_t f[4][4];
            #pragma unroll
            for (int b = 0; b < 4; b++)
                ldsm4(f[b][0], f[b][1], f[b][2], f[b][3],
                      bch + (uint32_t)(b * 16 * RSB) + boff + k * 32);
            #pragma unroll
            for (int b = 0; b < 4; b++) {
                mma16816(acc[2*b][0], acc[2*b][1], acc[2*b][2], acc[2*b][3],
                         af[k][0], af[k][1], af[k][2], af[k][3], f[b][0], f[b][1]);
                mma16816(acc[2*b+1][0], acc[2*b+1][1], acc[2*b+1][2], acc[2*b+1][3],
                         af[k][0], af[k][1], af[k][2], af[k][3], f[b][2], f[b][3]);
            }
        }

        // ---- scores + gated top-2 ----
        const int cb = t * CHUNK_N;
        #pragma unroll
        for (int s = 0; s < 8; s++) {
            int colbase = cb + (s >> 1) * 16 + (s & 1) * 8 + q2;
            float2 cs = *(float2*)&s_csqr[colbase];
            float vA0 = fmaf(-2.f, acc[s][0], cs.x);
            float vA1 = fmaf(-2.f, acc[s][1], cs.y);
            float vB0 = fmaf(-2.f, acc[s][2], cs.x);
            float vB1 = fmaf(-2.f, acc[s][3], cs.y);
            if (fminf(vA0, vA1) < sA2) {
                ins2(vA0, colbase,     sA1, iA1, sA2, iA2);
                ins2(vA1, colbase + 1, sA1, iA1, sA2, iA2);
            }
            if (fminf(vB0, vB1) < sB2) {
                ins2(vB0, colbase,     sB1, iB1, sB2, iB2);
                ins2(vB1, colbase + 1, sB1, iB1, sB2, iB2);
            }
        }
    }

    // ---- quad merge -> TRUE row top-2 ----
    #pragma unroll
    for (int d = 1; d <= 2; d <<= 1) {
        float t1 = __shfl_xor_sync(~0u, sA1, d); int j1 = __shfl_xor_sync(~0u, iA1, d);
        float t2 = __shfl_xor_sync(~0u, sA2, d); int j2 = __shfl_xor_sync(~0u, iA2, d);
        ins2(t1, j1, sA1, iA1, sA2, iA2);
        ins2(t2, j2, sA1, iA1, sA2, iA2);
        t1 = __shfl_xor_sync(~0u, sB1, d); j1 = __shfl_xor_sync(~0u, iB1, d);
        t2 = __shfl_xor_sync(~0u, sB2, d); j2 = __shfl_xor_sync(~0u, iB2, d);
        ins2(t1, j1, sB1, iB1, sB2, iB2);
        ins2(t2, j2, sB1, iB1, sB2, iB2);
    }
    if ((l & 3) == 0) {
        int rA = w * 16 + (l >> 2);
        s_m[rA] = make_float2(sA1, sA2);
        s_i[rA] = make_int2(iA1, iA2);
        int rB = rA + 8;
        s_m[rB] = make_float2(sB1, sB2);
        s_i[rB] = make_int2(iB1, iB2);
    }
    __syncthreads();

    // ---- certification (threads 0..127, one row each) ----
    if (tid < ROWS_PER_CTA) {
        const float4* x4 = (const float4*)(inp + (size_t)(row0 + tid) * D);
        float xs = 0.0f, xl2 = 0.0f;
        #pragma unroll
        for (int i = 0; i < 16; i++) {
            float4 v = x4[i];
            xs += v.x * v.x + v.y * v.y + v.z * v.z + v.w * v.w;
            uint32_t h0 = packh(v.x, v.y), h1 = packh(v.z, v.w);
            float2 f0 = unph(h0), f1 = unph(h1);
            float r0 = v.x - f0.x, r1 = v.y - f0.y;
            float r2 = v.z - f1.x, r3 = v.w - f1.y;
            xl2 += r0 * r0 + r1 * r1 + r2 * r2 + r3 * r3;
        }
        float xn = sqrtf(xs), xln = sqrtf(xl2);
        float maxC = sqrtf(g_maxc2), maxCl = sqrtf(g_maxcl2);
        // |approx - exact| <= 2*(||xl||*maxC + ||xh||*maxCl), ||xh||<=||x||+||xl||
        float margin = 2.02f * (xln * maxC + (xn + xln) * maxCl) + 1e-4f;

        float2 sm = s_m[tid];
        if (sm.y - sm.x > margin) {
            s_bidx[tid] = s_i[tid].x;            // certified winner
        } else {
            int p = atomicAdd(s_cnt, 1);         // needs exact resolution
            s_list[p] = tid;
        }
    }
    __syncthreads();

    // ---- cooperative exact scan for unresolved rows (all 256 threads) ----
    const int ncand = *s_cnt;
    for (int ci = 0; ci < ncand; ci++) {
        int crow = s_list[ci];
        const float4* cx = (const float4*)(inp + (size_t)(row0 + crow) * D);
        float bs = 3.4e38f; int bi = 0;
        #pragma unroll 1
        for (int c = 0; c < KCODES / TPB; c++) {
            int j = tid + TPB * c;
            const float4* cp = (const float4*)(codebook + (size_t)j * D);
            float dot = 0.0f;
            #pragma unroll
            for (int i = 0; i < 16; i++) {
                float4 a = cx[i], b = cp[i];
                dot += a.x * b.x + a.y * b.y + a.z * b.z + a.w * b.w;
            }
            float e = fmaf(-2.0f, dot, s_csqr[j]);
            if (e < bs || (e == bs && j < bi)) { bs = e; bi = j; }
        }
        #pragma unroll
        for (int o = 16; o > 0; o >>= 1) {
            float os = __shfl_down_sync(~0u, bs, o);
            int   oi = __shfl_down_sync(~0u, bi, o);
            if (os < bs || (os == bs && oi < bi)) { bs = os; bi = oi; }
        }
        if (l == 0) { s_reds[w] = bs; s_redi[w] = bi; }
        __syncthreads();
        if (tid == 0) {
            float fb = s_reds[0]; int fi = s_redi[0];
            #pragma unroll
            for (int ww = 1; ww < 8; ww++) {
                if (s_reds[ww] < fb || (s_reds[ww] == fb && s_redi[ww] < fi)) {
                    fb = s_reds[ww]; fi = s_redi[ww];
                }
            }
            s_bidx[crow] = fi;
        }
        __syncthreads();
    }

    // ---- outputs: z_q + idx + loss (threads 0..127) ----
    float err = 0.0f;
    if (tid < ROWS_PER_CTA) {
        int row = row0 + tid;
        int bidx = s_bidx[tid];
        const float4* x4 = (const float4*)(inp + (size_t)row * D);
        float q[D];
        const float4* q4 = (const float4*)(codebook + (size_t)bidx * D);
        #pragma unroll
        for (int i = 0; i < 16; i++) {
            float4 qq = q4[i];
            float4 x = x4[i];
            q[4 * i + 0] = qq.x; q[4 * i + 1] = qq.y;
            q[4 * i + 2] = qq.z; q[4 * i + 3] = qq.w;
            float dx = x.x - qq.x, dy = x.y - qq.y;
            float dz = x.z - qq.z, dw = x.w - qq.w;
            err += dx * dx + dy * dy + dz * dz + dw * dw;
        }
        // z_q at out+1 (4B offset): i=0,1,2,63 scalar; i=3..62 aligned float4
        float* orow = out + 1 + (size_t)row * D;
        orow[0] = q[0]; orow[1] = q[1]; orow[2] = q[2];
        #pragma unroll
        for (int b = 0; b < 15; b++) {
            int i = 3 + 4 * b;
            *(float4*)(orow + i) = make_float4(q[i], q[i + 1], q[i + 2], q[i + 3]);
        }
        orow[63] = q[63];
        out[1 + (size_t)n_rows * D + row] = (float)bidx;
    }
    #pragma unroll
    for (int off = 16; off > 0; off >>= 1)
        err += __shfl_down_sync(0xffffffffu, err, off);
    if ((tid & 31) == 0 && err != 0.0f)
        atomicAdd(&g_loss_accum, (double)err);

    // ---- last CTA finalizes loss ----
    __syncthreads();
    if (tid == 0) {
        __threadfence();
        unsigned tkt = atomicAdd(&g_ticket, 1u);
        if (tkt == gridDim.x - 1) {
            __threadfence();
            double L = g_loss_accum;
            out[0] = (float)(L * (1.25 / ((double)n_rows * (double)D)));
            g_loss_accum = 0.0;
            g_ticket = 0u;
        }
    }
}

extern "C" void kernel_launch(void* const* d_in, const int* in_sizes, int n_in,
                              void* d_out, int out_size) {
    const float* inp = (const float*)d_in[0];
    const float* codebook = (const float*)d_in[1];
    float* out = (float*)d_out;
    const int n_rows = in_sizes[0] / D;   // 131072

    static bool attr_done = false;
    if (!attr_done) {
        cudaFuncSetAttribute(vq_main_kernel,
                             cudaFuncAttributeMaxDynamicSharedMemorySize,
                             SMEM_TOTAL);
        attr_done = true;
    }
    vq_prep_kernel<<<(KCODES + 255) / 256, 256>>>(codebook);
    vq_main_kernel<<<n_rows / ROWS_PER_CTA, TPB, SMEM_TOTAL>>>(inp, codebook,
                                                               out, n_rows);
    (void)n_in; (void)out_size;
}